// round 13
// baseline (speedup 1.0000x reference)
#include <cuda_runtime.h>
#include <cuda_fp16.h>
#include <math.h>
#include <stdint.h>

#define NE 8
#define DIM 1024
#define DFF 4096
#define MAXN 4096
#define MAXA (2*MAXN)
#define RT 16   // row tiles per expert (max 2048 rows; mean 1024, sigma~30)

// ---------------- scratch (device globals: allocation-free) ----------------
__device__ __half g_Xh[(size_t)MAXA * DIM];
__device__ __half g_Hh[(size_t)MAXA * DFF];
__device__ __half g_W1h[(size_t)NE * DIM * DFF];
__device__ __half g_W2h[(size_t)NE * DFF * DIM];
__device__ int   g_cnt[NE];
__device__ int   g_off[NE];
__device__ int   g_cur[NE];
__device__ int   g_tope[MAXA];
__device__ float g_topg[MAXA];
__device__ int   g_rowtok[MAXA];
__device__ float g_rowgate[MAXA];

// ---------------- helpers ----------------
__device__ __forceinline__ float gelu_exact(float v) {
    return 0.5f * v * (1.0f + erff(v * 0.70710678118654752f));
}
__device__ __forceinline__ void cp16(uint32_t saddr, const void* gsrc, bool pred) {
    int sz = pred ? 16 : 0;
    asm volatile("cp.async.cg.shared.global [%0], [%1], 16, %2;\n"
                 :: "r"(saddr), "l"(gsrc), "r"(sz));
}
#define CP_COMMIT() asm volatile("cp.async.commit_group;\n")
#define CP_WAIT1()  asm volatile("cp.async.wait_group 1;\n")

__device__ __forceinline__ void ldsm_x4(unsigned r[4], uint32_t addr) {
    asm volatile("ldmatrix.sync.aligned.m8n8.x4.shared.b16 {%0,%1,%2,%3}, [%4];"
                 : "=r"(r[0]), "=r"(r[1]), "=r"(r[2]), "=r"(r[3]) : "r"(addr));
}
__device__ __forceinline__ void ldsm_x4t(unsigned r[4], uint32_t addr) {
    asm volatile("ldmatrix.sync.aligned.m8n8.x4.trans.shared.b16 {%0,%1,%2,%3}, [%4];"
                 : "=r"(r[0]), "=r"(r[1]), "=r"(r[2]), "=r"(r[3]) : "r"(addr));
}
__device__ __forceinline__ void mma_f16(float c[4], const unsigned a[4], const unsigned b[2]) {
    asm volatile(
        "mma.sync.aligned.m16n8k16.row.col.f32.f16.f16.f32 "
        "{%0,%1,%2,%3}, {%4,%5,%6,%7}, {%8,%9}, {%0,%1,%2,%3};\n"
        : "+f"(c[0]), "+f"(c[1]), "+f"(c[2]), "+f"(c[3])
        : "r"(a[0]), "r"(a[1]), "r"(a[2]), "r"(a[3]), "r"(b[0]), "r"(b[1]));
}
__device__ __forceinline__ void red_add_v2(float* p, float a, float b) {
    asm volatile("red.global.add.v2.f32 [%0], {%1, %2};"
                 :: "l"(p), "f"(a), "f"(b) : "memory");
}

// ---------------- kernel 1: reset ----------------
__global__ void reset_kernel() {
    if (threadIdx.x < NE) g_cnt[threadIdx.x] = 0;
}

// ---------------- kernel 2: routing ----------------
// top-2 on SIGMOID GATES (saturate to 1.0f; logit std ~32), lowest-index
// tie-break to match jax.lax.top_k. (fp32 throughout — do not change.)
__global__ void route_kernel(const float* __restrict__ x,
                             const float* __restrict__ cent) {
    __shared__ float su[DIM];
    __shared__ float slog[NE];
    const int tok = blockIdx.x;
    const float* u = x + (size_t)tok * DIM;
    for (int i = threadIdx.x; i < DIM; i += blockDim.x) su[i] = u[i];
    __syncthreads();

    const int w = threadIdx.x >> 5, lane = threadIdx.x & 31;
    const float* c = cent + (size_t)w * DIM;
    float s = 0.f;
    for (int i = lane; i < DIM; i += 32) s += su[i] * c[i];
    #pragma unroll
    for (int o = 16; o; o >>= 1) s += __shfl_xor_sync(0xffffffffu, s, o);
    if (lane == 0) slog[w] = s;
    __syncthreads();

    if (threadIdx.x == 0) {
        float gate[NE];
        #pragma unroll
        for (int e = 0; e < NE; e++) gate[e] = 1.0f / (1.0f + expf(-slog[e]));
        int e1 = 0; float v1 = gate[0];
        #pragma unroll
        for (int e = 1; e < NE; e++) if (gate[e] > v1) { v1 = gate[e]; e1 = e; }
        int e2 = -1; float v2 = -1.0f;
        #pragma unroll
        for (int e = 0; e < NE; e++) if (e != e1 && gate[e] > v2) { v2 = gate[e]; e2 = e; }
        float inv = 1.0f / (v1 + v2);
        g_tope[2*tok + 0] = e1;  g_topg[2*tok + 0] = v1 * inv;
        g_tope[2*tok + 1] = e2;  g_topg[2*tok + 1] = v2 * inv;
        atomicAdd(&g_cnt[e1], 1);
        atomicAdd(&g_cnt[e2], 1);
    }
}

// ---------------- kernel 3: scan ----------------
__global__ void scan_kernel() {
    if (threadIdx.x == 0) {
        int o = 0;
        #pragma unroll
        for (int e = 0; e < NE; e++) { g_off[e] = o; g_cur[e] = o; o += g_cnt[e]; }
    }
}

// ---------------- kernel 4: permute/gather (fp32 -> fp16) ----------------
__global__ void permute_kernel(const float* __restrict__ x) {
    __shared__ int spos;
    const int a = blockIdx.x;
    if (threadIdx.x == 0) {
        int e = g_tope[a];
        int p = atomicAdd(&g_cur[e], 1);
        g_rowtok[p]  = a >> 1;
        g_rowgate[p] = g_topg[a];
        spos = p;
    }
    __syncthreads();
    const int p = spos;
    const float4* src = (const float4*)(x + (size_t)(a >> 1) * DIM);
    __half2* dst = (__half2*)(g_Xh + (size_t)p * DIM);
    for (int i = threadIdx.x; i < DIM / 4; i += blockDim.x) {
        float4 v = src[i];
        dst[2*i    ] = __floats2half2_rn(v.x, v.y);
        dst[2*i + 1] = __floats2half2_rn(v.z, v.w);
    }
}

// ---------------- kernel 5: init output with gate-weighted b2 ----------------
__global__ void outinit_kernel(const float* __restrict__ b2,
                               float* __restrict__ out) {
    const int tok = blockIdx.x;
    const int e1 = g_tope[2*tok], e2 = g_tope[2*tok + 1];
    const float g1 = g_topg[2*tok], g2 = g_topg[2*tok + 1];
    const float* p1 = b2 + (size_t)e1 * DIM;
    const float* p2 = b2 + (size_t)e2 * DIM;
    float* o = out + (size_t)tok * DIM;
    for (int i = threadIdx.x; i < DIM; i += blockDim.x)
        o[i] = g1 * p1[i] + g2 * p2[i];
}

// ---------------- kernel: fp32 -> fp16 weight convert ----------------
__global__ void convert_half_kernel(const float* __restrict__ src,
                                    __half* __restrict__ dst, size_t n) {
    size_t idx = ((size_t)blockIdx.x * blockDim.x + threadIdx.x) * 8;
    if (idx < n) {
        float4 v0 = *(const float4*)(src + idx);
        float4 v1 = *(const float4*)(src + idx + 4);
        __half2 h[4];
        h[0] = __floats2half2_rn(v0.x, v0.y);
        h[1] = __floats2half2_rn(v0.z, v0.w);
        h[2] = __floats2half2_rn(v1.x, v1.y);
        h[3] = __floats2half2_rn(v1.z, v1.w);
        *(uint4*)(dst + idx) = *(uint4*)h;
    }
}

// ---------------- GEMM: fp16 mma.m16n8k16, 128x128x64 tiles, 3-stage cp.async ----------------
// 256 threads, 8 warps (4M x 2N), warp tile 32x64 (round-11 mainloop — best known).
// ebase: first expert handled by this launch (gridDim.y / RT experts).
// PHASE 2 runs split-K via blockIdx.z (slices concurrent; atomic adds commute).
template<int KDIM, int NDIM, int PHASE, int SPLITK>
__global__ void __launch_bounds__(256, 2)
gemm_f16_kernel(const __half* __restrict__ Wh,
                const float* __restrict__ biasAll,
                float* __restrict__ out, int ebase) {
    constexpr int BM = 128, BN = 128, BK = 64, STAGES = 3;
    constexpr int KSLICE = KDIM / SPLITK;
    constexpr int ASTR = 144;
    constexpr int BSTR = 272;
    constexpr int ABYTES = BM * ASTR;
    constexpr int BBYTES = BK * BSTR;
    constexpr int STAGE  = ABYTES + BBYTES;

    extern __shared__ char smem_raw[];
    uint32_t sb = (uint32_t)__cvta_generic_to_shared(smem_raw);
    sb = (sb + 127u) & ~127u;

    const int e  = ebase + blockIdx.y / RT;
    const int rt = blockIdx.y % RT;
    const int cnt = g_cnt[e];
    if (rt * BM >= cnt) return;
    const int row0 = g_off[e] + rt * BM;
    int nrows = cnt - rt * BM; if (nrows > BM) nrows = BM;
    const int col0 = blockIdx.x * BN;
    const int k0   = blockIdx.z * KSLICE;

    const __half* Aptr = (PHASE == 1 ? g_Xh : g_Hh) + (size_t)row0 * KDIM + k0;
    const __half* Bptr = Wh + (size_t)e * KDIM * NDIM + (size_t)k0 * NDIM;

    const int tid = threadIdx.x;
    const int w = tid >> 5, lane = tid & 31;
    const int grp = lane >> 2, qid = lane & 3;
    const int wm = (w >> 1) * 32;
    const int wn = (w & 1) * 64;
    const int KT = KSLICE / BK;

    float acc[2][8][4];
    #pragma unroll
    for (int tm = 0; tm < 2; tm++)
        #pragma unroll
        for (int tn = 0; tn < 8; tn++)
            #pragma unroll
            for (int i = 0; i < 4; i++) acc[tm][tn][i] = 0.f;

    auto issue = [&](int kt) {
        if (kt < KT) {
            const int s = kt % STAGES;
            const uint32_t ab = sb + s * STAGE;
            const uint32_t bb = ab + ABYTES;
            const int kofs = kt * BK;
            #pragma unroll
            for (int j = 0; j < 4; j++) {
                const int v = tid + j * 256;
                const int r = v >> 3, c = v & 7;
                const bool ok = r < nrows;
                cp16(ab + r * ASTR + c * 16,
                     Aptr + (size_t)r * KDIM + kofs + c * 8, ok);
            }
            #pragma unroll
            for (int j = 0; j < 4; j++) {
                const int v = tid + j * 256;
                const int k = v >> 4, c = v & 15;
                cp16(bb + k * BSTR + c * 16,
                     Bptr + (size_t)(kofs + k) * NDIM + col0 + c * 8, true);
            }
        }
        CP_COMMIT();
    };

    issue(0); issue(1);

    const uint32_t a_lrow = lane & 15;
    const uint32_t a_lcol = (lane >> 4) * 16;
    const uint32_t b_lrow = lane & 15;
    const uint32_t b_lcol = (lane >> 4) * 16;

    for (int kt = 0; kt < KT; kt++) {
        CP_WAIT1();
        __syncthreads();
        issue(kt + 2);

        const int s = kt % STAGES;
        const uint32_t ab = sb + s * STAGE;
        const uint32_t bb = ab + ABYTES;

        #pragma unroll
        for (int ks = 0; ks < 4; ks++) {
            unsigned af[2][4], bf[4][4];
            #pragma unroll
            for (int mt = 0; mt < 2; mt++)
                ldsm_x4(af[mt], ab + (wm + mt * 16 + a_lrow) * ASTR + a_lcol + ks * 32);
            #pragma unroll
            for (int np = 0; np < 4; np++)
                ldsm_x4t(bf[np], bb + (ks * 16 + b_lrow) * BSTR + (wn + np * 16) * 2 + b_lcol);
            #pragma unroll
            for (int mt = 0; mt < 2; mt++)
                #pragma unroll
                for (int nt = 0; nt < 8; nt++)
                    mma_f16(acc[mt][nt], af[mt], &bf[nt >> 1][(nt & 1) * 2]);
        }
    }

    if (PHASE == 1) {
        const float* bias = biasAll + (size_t)e * NDIM + col0;
        #pragma unroll
        for (int mt = 0; mt < 2; mt++) {
            #pragma unroll
            for (int hf = 0; hf < 2; hf++) {
                const int rl = wm + mt * 16 + grp + hf * 8;
                if (rl < nrows) {
                    __half* hrow = g_Hh + (size_t)(row0 + rl) * NDIM + col0;
                    #pragma unroll
                    for (int nt = 0; nt < 8; nt++) {
                        const int c = wn + nt * 8 + qid * 2;
                        float v0 = gelu_exact(acc[mt][nt][hf*2    ] + bias[c]);
                        float v1 = gelu_exact(acc[mt][nt][hf*2 + 1] + bias[c + 1]);
                        *(__half2*)(hrow + c) = __floats2half2_rn(v0, v1);
                    }
                }
            }
        }
    } else {
        #pragma unroll
        for (int mt = 0; mt < 2; mt++) {
            #pragma unroll
            for (int hf = 0; hf < 2; hf++) {
                const int rl = wm + mt * 16 + grp + hf * 8;
                if (rl < nrows) {
                    const int p = row0 + rl;
                    const float g = g_rowgate[p];
                    float* orow = out + (size_t)g_rowtok[p] * DIM + col0;
                    #pragma unroll
                    for (int nt = 0; nt < 8; nt++) {
                        const int c = wn + nt * 8 + qid * 2;
                        red_add_v2(orow + c,
                                   g * acc[mt][nt][hf*2],
                                   g * acc[mt][nt][hf*2 + 1]);
                    }
                }
            }
        }
    }
}

// ---------------- launch: 4-stage expert pipeline across two streams ----------------
extern "C" void kernel_launch(void* const* d_in, const int* in_sizes, int n_in,
                              void* d_out, int out_size) {
    const float* x    = (const float*)d_in[0];
    const float* cent = (const float*)d_in[1];
    const float* W1   = (const float*)d_in[2];
    const float* b1   = (const float*)d_in[3];
    const float* W2   = (const float*)d_in[4];
    const float* b2   = (const float*)d_in[5];
    float* out = (float*)d_out;

    const int n = in_sizes[0] / DIM;   // 4096 tokens

    const int smem_bytes = 3 * 35840 + 128;   // ~105.1 KB -> 2 CTAs/SM
    static cudaStream_t sB = nullptr;
    static cudaEvent_t eFork = nullptr, eRoute = nullptr, eW1 = nullptr,
                       eW2 = nullptr, eOut = nullptr, eJoin = nullptr;
    static cudaEvent_t e1[4] = {nullptr, nullptr, nullptr, nullptr};
    if (sB == nullptr) {
        cudaFuncSetAttribute(gemm_f16_kernel<DIM, DFF, 1, 1>,
                             cudaFuncAttributeMaxDynamicSharedMemorySize, smem_bytes);
        cudaFuncSetAttribute(gemm_f16_kernel<DFF, DIM, 2, 4>,
                             cudaFuncAttributeMaxDynamicSharedMemorySize, smem_bytes);
        cudaStreamCreateWithFlags(&sB, cudaStreamNonBlocking);
        cudaEventCreateWithFlags(&eFork,  cudaEventDisableTiming);
        cudaEventCreateWithFlags(&eRoute, cudaEventDisableTiming);
        cudaEventCreateWithFlags(&eW1,    cudaEventDisableTiming);
        cudaEventCreateWithFlags(&eW2,    cudaEventDisableTiming);
        cudaEventCreateWithFlags(&eOut,   cudaEventDisableTiming);
        cudaEventCreateWithFlags(&eJoin,  cudaEventDisableTiming);
        for (int i = 0; i < 4; i++)
            cudaEventCreateWithFlags(&e1[i], cudaEventDisableTiming);
    }

    __half* w1h; cudaGetSymbolAddress((void**)&w1h, g_W1h);
    __half* w2h; cudaGetSymbolAddress((void**)&w2h, g_W2h);

    const size_t welems = (size_t)NE * DIM * DFF;
    const int cblocks = (int)(welems / 8 / 256);

    // fork stream B
    cudaEventRecord(eFork, 0);
    cudaStreamWaitEvent(sB, eFork, 0);

    // ---- stream B: weight converts ----
    convert_half_kernel<<<cblocks, 256, 0, sB>>>(W1, w1h, welems);
    cudaEventRecord(eW1, sB);
    convert_half_kernel<<<cblocks, 256, 0, sB>>>(W2, w2h, welems);
    cudaEventRecord(eW2, sB);

    // ---- main stream: routing chain ----
    reset_kernel<<<1, 32>>>();
    route_kernel<<<n, 256>>>(x, cent);
    cudaEventRecord(eRoute, 0);
    scan_kernel<<<1, 1>>>();
    permute_kernel<<<2 * n, 256>>>(x);

    // ---- stream B: outinit (needs route only) ----
    cudaStreamWaitEvent(sB, eRoute, 0);
    outinit_kernel<<<n, 256, 0, sB>>>(b2, out);
    cudaEventRecord(eOut, sB);

    // ---- main stream: gemm1 in 4 chunks of 2 experts; events after each ----
    cudaStreamWaitEvent(0, eW1, 0);
    dim3 g1(DFF / 128, 2 * RT, 1);
    for (int c = 0; c < 4; c++) {
        gemm_f16_kernel<DIM, DFF, 1, 1><<<g1, 256, smem_bytes>>>(w1h, b1, nullptr, 2 * c);
        cudaEventRecord(e1[c], 0);
    }

    // ---- stream B: gemm2 chunks, each gated on its gemm1 chunk ----
    cudaStreamWaitEvent(sB, eW2, 0);     // weights ready (no-op: sB in-order)
    dim3 g2(DIM / 128, 2 * RT, 4);       // split-K x4, slices concurrent
    for (int c = 0; c < 4; c++) {
        cudaStreamWaitEvent(sB, e1[c], 0);
        gemm_f16_kernel<DFF, DIM, 2, 4><<<g2, 256, smem_bytes, sB>>>(w2h, nullptr, out, 2 * c);
    }
    cudaEventRecord(eJoin, sB);

    // join back to main (capture-origin) stream
    cudaStreamWaitEvent(0, eJoin, 0);
}

// round 14
// speedup vs baseline: 1.0236x; 1.0236x over previous
#include <cuda_runtime.h>
#include <cuda_fp16.h>
#include <math.h>
#include <stdint.h>

#define NE 8
#define DIM 1024
#define DFF 4096
#define MAXN 4096
#define MAXA (2*MAXN)
#define RT 16   // row tiles per expert (max 2048 rows; index-skewed counts reach ~1400)

// ---------------- scratch (device globals: allocation-free) ----------------
__device__ __half g_Xh[(size_t)MAXA * DIM];
__device__ __half g_Hh[(size_t)MAXA * DFF];
__device__ __half g_W1h[(size_t)NE * DIM * DFF];
__device__ __half g_W2h[(size_t)NE * DFF * DIM];
__device__ int   g_cnt[NE];
__device__ int   g_off[NE];
__device__ int   g_cur[NE];
__device__ int   g_tope[MAXA];
__device__ float g_topg[MAXA];
__device__ int   g_rowtok[MAXA];
__device__ float g_rowgate[MAXA];

// ---------------- helpers ----------------
__device__ __forceinline__ float gelu_exact(float v) {
    return 0.5f * v * (1.0f + erff(v * 0.70710678118654752f));
}
__device__ __forceinline__ void cp16(uint32_t saddr, const void* gsrc, bool pred) {
    int sz = pred ? 16 : 0;
    asm volatile("cp.async.cg.shared.global [%0], [%1], 16, %2;\n"
                 :: "r"(saddr), "l"(gsrc), "r"(sz));
}
#define CP_COMMIT() asm volatile("cp.async.commit_group;\n")
#define CP_WAIT1()  asm volatile("cp.async.wait_group 1;\n")

__device__ __forceinline__ void ldsm_x4(unsigned r[4], uint32_t addr) {
    asm volatile("ldmatrix.sync.aligned.m8n8.x4.shared.b16 {%0,%1,%2,%3}, [%4];"
                 : "=r"(r[0]), "=r"(r[1]), "=r"(r[2]), "=r"(r[3]) : "r"(addr));
}
__device__ __forceinline__ void ldsm_x4t(unsigned r[4], uint32_t addr) {
    asm volatile("ldmatrix.sync.aligned.m8n8.x4.trans.shared.b16 {%0,%1,%2,%3}, [%4];"
                 : "=r"(r[0]), "=r"(r[1]), "=r"(r[2]), "=r"(r[3]) : "r"(addr));
}
__device__ __forceinline__ void mma_f16(float c[4], const unsigned a[4], const unsigned b[2]) {
    asm volatile(
        "mma.sync.aligned.m16n8k16.row.col.f32.f16.f16.f32 "
        "{%0,%1,%2,%3}, {%4,%5,%6,%7}, {%8,%9}, {%0,%1,%2,%3};\n"
        : "+f"(c[0]), "+f"(c[1]), "+f"(c[2]), "+f"(c[3])
        : "r"(a[0]), "r"(a[1]), "r"(a[2]), "r"(a[3]), "r"(b[0]), "r"(b[1]));
}
__device__ __forceinline__ void red_add_v2(float* p, float a, float b) {
    asm volatile("red.global.add.v2.f32 [%0], {%1, %2};"
                 :: "l"(p), "f"(a), "f"(b) : "memory");
}

// ---------------- kernel 1: reset ----------------
__global__ void reset_kernel() {
    if (threadIdx.x < NE) g_cnt[threadIdx.x] = 0;
}

// ---------------- kernel 2: routing ----------------
// top-2 on SIGMOID GATES (saturate to 1.0f; logit std ~32), lowest-index
// tie-break to match jax.lax.top_k. (fp32 throughout — do not change.)
__global__ void route_kernel(const float* __restrict__ x,
                             const float* __restrict__ cent) {
    __shared__ float su[DIM];
    __shared__ float slog[NE];
    const int tok = blockIdx.x;
    const float* u = x + (size_t)tok * DIM;
    for (int i = threadIdx.x; i < DIM; i += blockDim.x) su[i] = u[i];
    __syncthreads();

    const int w = threadIdx.x >> 5, lane = threadIdx.x & 31;
    const float* c = cent + (size_t)w * DIM;
    float s = 0.f;
    for (int i = lane; i < DIM; i += 32) s += su[i] * c[i];
    #pragma unroll
    for (int o = 16; o; o >>= 1) s += __shfl_xor_sync(0xffffffffu, s, o);
    if (lane == 0) slog[w] = s;
    __syncthreads();

    if (threadIdx.x == 0) {
        float gate[NE];
        #pragma unroll
        for (int e = 0; e < NE; e++) gate[e] = 1.0f / (1.0f + expf(-slog[e]));
        int e1 = 0; float v1 = gate[0];
        #pragma unroll
        for (int e = 1; e < NE; e++) if (gate[e] > v1) { v1 = gate[e]; e1 = e; }
        int e2 = -1; float v2 = -1.0f;
        #pragma unroll
        for (int e = 0; e < NE; e++) if (e != e1 && gate[e] > v2) { v2 = gate[e]; e2 = e; }
        float inv = 1.0f / (v1 + v2);
        g_tope[2*tok + 0] = e1;  g_topg[2*tok + 0] = v1 * inv;
        g_tope[2*tok + 1] = e2;  g_topg[2*tok + 1] = v2 * inv;
        atomicAdd(&g_cnt[e1], 1);
        atomicAdd(&g_cnt[e2], 1);
    }
}

// ---------------- kernel 3: scan ----------------
__global__ void scan_kernel() {
    if (threadIdx.x == 0) {
        int o = 0;
        #pragma unroll
        for (int e = 0; e < NE; e++) { g_off[e] = o; g_cur[e] = o; o += g_cnt[e]; }
    }
}

// ---------------- kernel 4: permute/gather (fp32 -> fp16) ----------------
__global__ void permute_kernel(const float* __restrict__ x) {
    __shared__ int spos;
    const int a = blockIdx.x;
    if (threadIdx.x == 0) {
        int e = g_tope[a];
        int p = atomicAdd(&g_cur[e], 1);
        g_rowtok[p]  = a >> 1;
        g_rowgate[p] = g_topg[a];
        spos = p;
    }
    __syncthreads();
    const int p = spos;
    const float4* src = (const float4*)(x + (size_t)(a >> 1) * DIM);
    __half2* dst = (__half2*)(g_Xh + (size_t)p * DIM);
    for (int i = threadIdx.x; i < DIM / 4; i += blockDim.x) {
        float4 v = src[i];
        dst[2*i    ] = __floats2half2_rn(v.x, v.y);
        dst[2*i + 1] = __floats2half2_rn(v.z, v.w);
    }
}

// ---------------- kernel 5: init output with gate-weighted b2 ----------------
__global__ void outinit_kernel(const float* __restrict__ b2,
                               float* __restrict__ out) {
    const int tok = blockIdx.x;
    const int e1 = g_tope[2*tok], e2 = g_tope[2*tok + 1];
    const float g1 = g_topg[2*tok], g2 = g_topg[2*tok + 1];
    const float* p1 = b2 + (size_t)e1 * DIM;
    const float* p2 = b2 + (size_t)e2 * DIM;
    float* o = out + (size_t)tok * DIM;
    for (int i = threadIdx.x; i < DIM; i += blockDim.x)
        o[i] = g1 * p1[i] + g2 * p2[i];
}

// ---------------- kernel: fp32 -> fp16 weight convert ----------------
__global__ void convert_half_kernel(const float* __restrict__ src,
                                    __half* __restrict__ dst, size_t n) {
    size_t idx = ((size_t)blockIdx.x * blockDim.x + threadIdx.x) * 8;
    if (idx < n) {
        float4 v0 = *(const float4*)(src + idx);
        float4 v1 = *(const float4*)(src + idx + 4);
        __half2 h[4];
        h[0] = __floats2half2_rn(v0.x, v0.y);
        h[1] = __floats2half2_rn(v0.z, v0.w);
        h[2] = __floats2half2_rn(v1.x, v1.y);
        h[3] = __floats2half2_rn(v1.z, v1.w);
        *(uint4*)(dst + idx) = *(uint4*)h;
    }
}

// ---------------- GEMM: fp16 mma.m16n8k16, 128x128x64 tiles, 3-stage cp.async ----------------
// 256 threads, 8 warps (4M x 2N), warp tile 32x64 (round-11 mainloop — best known).
// Expert selection: e = ebase + (blockIdx.y / RT) * ESTRIDE — striding balances
// the index-skewed expert counts across the two pipeline chunks.
// PHASE 2 runs split-K via blockIdx.z (slices concurrent; atomic adds commute).
template<int KDIM, int NDIM, int PHASE, int SPLITK>
__global__ void __launch_bounds__(256, 2)
gemm_f16_kernel(const __half* __restrict__ Wh,
                const float* __restrict__ biasAll,
                float* __restrict__ out, int ebase, int estride) {
    constexpr int BM = 128, BN = 128, BK = 64, STAGES = 3;
    constexpr int KSLICE = KDIM / SPLITK;
    constexpr int ASTR = 144;
    constexpr int BSTR = 272;
    constexpr int ABYTES = BM * ASTR;
    constexpr int BBYTES = BK * BSTR;
    constexpr int STAGE  = ABYTES + BBYTES;

    extern __shared__ char smem_raw[];
    uint32_t sb = (uint32_t)__cvta_generic_to_shared(smem_raw);
    sb = (sb + 127u) & ~127u;

    const int e  = ebase + (blockIdx.y / RT) * estride;
    const int rt = blockIdx.y % RT;
    const int cnt = g_cnt[e];
    if (rt * BM >= cnt) return;
    const int row0 = g_off[e] + rt * BM;
    int nrows = cnt - rt * BM; if (nrows > BM) nrows = BM;
    const int col0 = blockIdx.x * BN;
    const int k0   = blockIdx.z * KSLICE;

    const __half* Aptr = (PHASE == 1 ? g_Xh : g_Hh) + (size_t)row0 * KDIM + k0;
    const __half* Bptr = Wh + (size_t)e * KDIM * NDIM + (size_t)k0 * NDIM;

    const int tid = threadIdx.x;
    const int w = tid >> 5, lane = tid & 31;
    const int grp = lane >> 2, qid = lane & 3;
    const int wm = (w >> 1) * 32;
    const int wn = (w & 1) * 64;
    const int KT = KSLICE / BK;

    float acc[2][8][4];
    #pragma unroll
    for (int tm = 0; tm < 2; tm++)
        #pragma unroll
        for (int tn = 0; tn < 8; tn++)
            #pragma unroll
            for (int i = 0; i < 4; i++) acc[tm][tn][i] = 0.f;

    auto issue = [&](int kt) {
        if (kt < KT) {
            const int s = kt % STAGES;
            const uint32_t ab = sb + s * STAGE;
            const uint32_t bb = ab + ABYTES;
            const int kofs = kt * BK;
            #pragma unroll
            for (int j = 0; j < 4; j++) {
                const int v = tid + j * 256;
                const int r = v >> 3, c = v & 7;
                const bool ok = r < nrows;
                cp16(ab + r * ASTR + c * 16,
                     Aptr + (size_t)r * KDIM + kofs + c * 8, ok);
            }
            #pragma unroll
            for (int j = 0; j < 4; j++) {
                const int v = tid + j * 256;
                const int k = v >> 4, c = v & 15;
                cp16(bb + k * BSTR + c * 16,
                     Bptr + (size_t)(kofs + k) * NDIM + col0 + c * 8, true);
            }
        }
        CP_COMMIT();
    };

    issue(0); issue(1);

    const uint32_t a_lrow = lane & 15;
    const uint32_t a_lcol = (lane >> 4) * 16;
    const uint32_t b_lrow = lane & 15;
    const uint32_t b_lcol = (lane >> 4) * 16;

    for (int kt = 0; kt < KT; kt++) {
        CP_WAIT1();
        __syncthreads();
        issue(kt + 2);

        const int s = kt % STAGES;
        const uint32_t ab = sb + s * STAGE;
        const uint32_t bb = ab + ABYTES;

        #pragma unroll
        for (int ks = 0; ks < 4; ks++) {
            unsigned af[2][4], bf[4][4];
            #pragma unroll
            for (int mt = 0; mt < 2; mt++)
                ldsm_x4(af[mt], ab + (wm + mt * 16 + a_lrow) * ASTR + a_lcol + ks * 32);
            #pragma unroll
            for (int np = 0; np < 4; np++)
                ldsm_x4t(bf[np], bb + (ks * 16 + b_lrow) * BSTR + (wn + np * 16) * 2 + b_lcol);
            #pragma unroll
            for (int mt = 0; mt < 2; mt++)
                #pragma unroll
                for (int nt = 0; nt < 8; nt++)
                    mma_f16(acc[mt][nt], af[mt], &bf[nt >> 1][(nt & 1) * 2]);
        }
    }

    if (PHASE == 1) {
        const float* bias = biasAll + (size_t)e * NDIM + col0;
        #pragma unroll
        for (int mt = 0; mt < 2; mt++) {
            #pragma unroll
            for (int hf = 0; hf < 2; hf++) {
                const int rl = wm + mt * 16 + grp + hf * 8;
                if (rl < nrows) {
                    __half* hrow = g_Hh + (size_t)(row0 + rl) * NDIM + col0;
                    #pragma unroll
                    for (int nt = 0; nt < 8; nt++) {
                        const int c = wn + nt * 8 + qid * 2;
                        float v0 = gelu_exact(acc[mt][nt][hf*2    ] + bias[c]);
                        float v1 = gelu_exact(acc[mt][nt][hf*2 + 1] + bias[c + 1]);
                        *(__half2*)(hrow + c) = __floats2half2_rn(v0, v1);
                    }
                }
            }
        }
    } else {
        #pragma unroll
        for (int mt = 0; mt < 2; mt++) {
            #pragma unroll
            for (int hf = 0; hf < 2; hf++) {
                const int rl = wm + mt * 16 + grp + hf * 8;
                if (rl < nrows) {
                    const int p = row0 + rl;
                    const float g = g_rowgate[p];
                    float* orow = out + (size_t)g_rowtok[p] * DIM + col0;
                    #pragma unroll
                    for (int nt = 0; nt < 8; nt++) {
                        const int c = wn + nt * 8 + qid * 2;
                        red_add_v2(orow + c,
                                   g * acc[mt][nt][hf*2],
                                   g * acc[mt][nt][hf*2 + 1]);
                    }
                }
            }
        }
    }
}

// ---------------- launch: round-12 topology + balanced (strided) expert chunks ----------------
extern "C" void kernel_launch(void* const* d_in, const int* in_sizes, int n_in,
                              void* d_out, int out_size) {
    const float* x    = (const float*)d_in[0];
    const float* cent = (const float*)d_in[1];
    const float* W1   = (const float*)d_in[2];
    const float* b1   = (const float*)d_in[3];
    const float* W2   = (const float*)d_in[4];
    const float* b2   = (const float*)d_in[5];
    float* out = (float*)d_out;

    const int n = in_sizes[0] / DIM;   // 4096 tokens

    const int smem_bytes = 3 * 35840 + 128;   // ~105.1 KB -> 2 CTAs/SM
    static cudaStream_t sB = nullptr;
    static cudaEvent_t eFork = nullptr, eRoute = nullptr, eW1 = nullptr,
                       eW2 = nullptr, eOut = nullptr, e1A = nullptr, eJoin = nullptr;
    if (sB == nullptr) {
        cudaFuncSetAttribute(gemm_f16_kernel<DIM, DFF, 1, 1>,
                             cudaFuncAttributeMaxDynamicSharedMemorySize, smem_bytes);
        cudaFuncSetAttribute(gemm_f16_kernel<DFF, DIM, 2, 4>,
                             cudaFuncAttributeMaxDynamicSharedMemorySize, smem_bytes);
        cudaStreamCreateWithFlags(&sB, cudaStreamNonBlocking);
        cudaEventCreateWithFlags(&eFork,  cudaEventDisableTiming);
        cudaEventCreateWithFlags(&eRoute, cudaEventDisableTiming);
        cudaEventCreateWithFlags(&eW1,    cudaEventDisableTiming);
        cudaEventCreateWithFlags(&eW2,    cudaEventDisableTiming);
        cudaEventCreateWithFlags(&eOut,   cudaEventDisableTiming);
        cudaEventCreateWithFlags(&e1A,    cudaEventDisableTiming);
        cudaEventCreateWithFlags(&eJoin,  cudaEventDisableTiming);
    }

    __half* w1h; cudaGetSymbolAddress((void**)&w1h, g_W1h);
    __half* w2h; cudaGetSymbolAddress((void**)&w2h, g_W2h);

    const size_t welems = (size_t)NE * DIM * DFF;
    const int cblocks = (int)(welems / 8 / 256);

    // fork stream B
    cudaEventRecord(eFork, 0);
    cudaStreamWaitEvent(sB, eFork, 0);

    // ---- stream B: weight converts ----
    convert_half_kernel<<<cblocks, 256, 0, sB>>>(W1, w1h, welems);
    cudaEventRecord(eW1, sB);
    convert_half_kernel<<<cblocks, 256, 0, sB>>>(W2, w2h, welems);
    cudaEventRecord(eW2, sB);

    // ---- main stream: routing chain ----
    reset_kernel<<<1, 32>>>();
    route_kernel<<<n, 256>>>(x, cent);
    cudaEventRecord(eRoute, 0);
    scan_kernel<<<1, 1>>>();
    permute_kernel<<<2 * n, 256>>>(x);

    // ---- stream B: outinit (needs route only) ----
    cudaStreamWaitEvent(sB, eRoute, 0);
    outinit_kernel<<<n, 256, 0, sB>>>(b2, out);
    cudaEventRecord(eOut, sB);

    // ---- main stream: gemm1 chunk A = experts {0,2,4,6}, chunk B = {1,3,5,7} ----
    cudaStreamWaitEvent(0, eW1, 0);
    dim3 g1(DFF / 128, 4 * RT, 1);
    gemm_f16_kernel<DIM, DFF, 1, 1><<<g1, 256, smem_bytes>>>(w1h, b1, nullptr, 0, 2);
    cudaEventRecord(e1A, 0);
    gemm_f16_kernel<DIM, DFF, 1, 1><<<g1, 256, smem_bytes>>>(w1h, b1, nullptr, 1, 2);

    // ---- stream B: gemm2 chunk A (overlaps gemm1 chunk B) ----
    cudaStreamWaitEvent(sB, e1A, 0);
    dim3 g2(DIM / 128, 4 * RT, 4);          // split-K x4, slices concurrent
    gemm_f16_kernel<DFF, DIM, 2, 4><<<g2, 256, smem_bytes, sB>>>(w2h, nullptr, out, 0, 2);
    cudaEventRecord(eJoin, sB);

    // ---- main stream: gemm2 chunk B (after gemm1B; needs w2h + outinit) ----
    cudaStreamWaitEvent(0, eW2, 0);
    cudaStreamWaitEvent(0, eOut, 0);
    gemm_f16_kernel<DFF, DIM, 2, 4><<<g2, 256, smem_bytes>>>(w2h, nullptr, out, 1, 2);

    // join stream B back to main
    cudaStreamWaitEvent(0, eJoin, 0);
}

// round 15
// speedup vs baseline: 1.0407x; 1.0167x over previous
#include <cuda_runtime.h>
#include <cuda_fp16.h>
#include <math.h>
#include <stdint.h>

#define NE 8
#define DIM 1024
#define DFF 4096
#define MAXN 4096
#define MAXA (2*MAXN)
#define RT 16   // row tiles per expert (max 2048 rows; index-skewed counts reach ~1400)

// ---------------- scratch (device globals: allocation-free) ----------------
__device__ __half g_Xh[(size_t)MAXA * DIM];
__device__ __half g_Hh[(size_t)MAXA * DFF];
__device__ __half g_W1h[(size_t)NE * DIM * DFF];
__device__ __half g_W2h[(size_t)NE * DFF * DIM];
__device__ int   g_cnt[NE];
__device__ int   g_off[NE];
__device__ int   g_cur[NE];
__device__ int   g_tope[MAXA];
__device__ float g_topg[MAXA];
__device__ int   g_rowtok[MAXA];
__device__ float g_rowgate[MAXA];

// ---------------- helpers ----------------
__device__ __forceinline__ float gelu_exact(float v) {
    return 0.5f * v * (1.0f + erff(v * 0.70710678118654752f));
}
__device__ __forceinline__ void cp16(uint32_t saddr, const void* gsrc, bool pred) {
    int sz = pred ? 16 : 0;
    asm volatile("cp.async.cg.shared.global [%0], [%1], 16, %2;\n"
                 :: "r"(saddr), "l"(gsrc), "r"(sz));
}
#define CP_COMMIT() asm volatile("cp.async.commit_group;\n")
#define CP_WAIT1()  asm volatile("cp.async.wait_group 1;\n")

__device__ __forceinline__ void ldsm_x4(unsigned r[4], uint32_t addr) {
    asm volatile("ldmatrix.sync.aligned.m8n8.x4.shared.b16 {%0,%1,%2,%3}, [%4];"
                 : "=r"(r[0]), "=r"(r[1]), "=r"(r[2]), "=r"(r[3]) : "r"(addr));
}
__device__ __forceinline__ void ldsm_x4t(unsigned r[4], uint32_t addr) {
    asm volatile("ldmatrix.sync.aligned.m8n8.x4.trans.shared.b16 {%0,%1,%2,%3}, [%4];"
                 : "=r"(r[0]), "=r"(r[1]), "=r"(r[2]), "=r"(r[3]) : "r"(addr));
}
__device__ __forceinline__ void mma_f16(float c[4], const unsigned a[4], const unsigned b[2]) {
    asm volatile(
        "mma.sync.aligned.m16n8k16.row.col.f32.f16.f16.f32 "
        "{%0,%1,%2,%3}, {%4,%5,%6,%7}, {%8,%9}, {%0,%1,%2,%3};\n"
        : "+f"(c[0]), "+f"(c[1]), "+f"(c[2]), "+f"(c[3])
        : "r"(a[0]), "r"(a[1]), "r"(a[2]), "r"(a[3]), "r"(b[0]), "r"(b[1]));
}
__device__ __forceinline__ void red_add_v2(float* p, float a, float b) {
    asm volatile("red.global.add.v2.f32 [%0], {%1, %2};"
                 :: "l"(p), "f"(a), "f"(b) : "memory");
}

// ---------------- kernel 1: reset ----------------
__global__ void reset_kernel() {
    if (threadIdx.x < NE) g_cnt[threadIdx.x] = 0;
}

// ---------------- kernel 2: routing ----------------
// top-2 on SIGMOID GATES (saturate to 1.0f; logit std ~32), lowest-index
// tie-break to match jax.lax.top_k. (fp32 throughout — do not change.)
__global__ void route_kernel(const float* __restrict__ x,
                             const float* __restrict__ cent) {
    __shared__ float su[DIM];
    __shared__ float slog[NE];
    const int tok = blockIdx.x;
    const float* u = x + (size_t)tok * DIM;
    for (int i = threadIdx.x; i < DIM; i += blockDim.x) su[i] = u[i];
    __syncthreads();

    const int w = threadIdx.x >> 5, lane = threadIdx.x & 31;
    const float* c = cent + (size_t)w * DIM;
    float s = 0.f;
    for (int i = lane; i < DIM; i += 32) s += su[i] * c[i];
    #pragma unroll
    for (int o = 16; o; o >>= 1) s += __shfl_xor_sync(0xffffffffu, s, o);
    if (lane == 0) slog[w] = s;
    __syncthreads();

    if (threadIdx.x == 0) {
        float gate[NE];
        #pragma unroll
        for (int e = 0; e < NE; e++) gate[e] = 1.0f / (1.0f + expf(-slog[e]));
        int e1 = 0; float v1 = gate[0];
        #pragma unroll
        for (int e = 1; e < NE; e++) if (gate[e] > v1) { v1 = gate[e]; e1 = e; }
        int e2 = -1; float v2 = -1.0f;
        #pragma unroll
        for (int e = 0; e < NE; e++) if (e != e1 && gate[e] > v2) { v2 = gate[e]; e2 = e; }
        float inv = 1.0f / (v1 + v2);
        g_tope[2*tok + 0] = e1;  g_topg[2*tok + 0] = v1 * inv;
        g_tope[2*tok + 1] = e2;  g_topg[2*tok + 1] = v2 * inv;
        atomicAdd(&g_cnt[e1], 1);
        atomicAdd(&g_cnt[e2], 1);
    }
}

// ---------------- kernel 3: scan ----------------
__global__ void scan_kernel() {
    if (threadIdx.x == 0) {
        int o = 0;
        #pragma unroll
        for (int e = 0; e < NE; e++) { g_off[e] = o; g_cur[e] = o; o += g_cnt[e]; }
    }
}

// ---------------- kernel 4: permute/gather (fp32 -> fp16) ----------------
__global__ void permute_kernel(const float* __restrict__ x) {
    __shared__ int spos;
    const int a = blockIdx.x;
    if (threadIdx.x == 0) {
        int e = g_tope[a];
        int p = atomicAdd(&g_cur[e], 1);
        g_rowtok[p]  = a >> 1;
        g_rowgate[p] = g_topg[a];
        spos = p;
    }
    __syncthreads();
    const int p = spos;
    const float4* src = (const float4*)(x + (size_t)(a >> 1) * DIM);
    __half2* dst = (__half2*)(g_Xh + (size_t)p * DIM);
    for (int i = threadIdx.x; i < DIM / 4; i += blockDim.x) {
        float4 v = src[i];
        dst[2*i    ] = __floats2half2_rn(v.x, v.y);
        dst[2*i + 1] = __floats2half2_rn(v.z, v.w);
    }
}

// ---------------- kernel 5: init output with gate-weighted b2 ----------------
__global__ void outinit_kernel(const float* __restrict__ b2,
                               float* __restrict__ out) {
    const int tok = blockIdx.x;
    const int e1 = g_tope[2*tok], e2 = g_tope[2*tok + 1];
    const float g1 = g_topg[2*tok], g2 = g_topg[2*tok + 1];
    const float* p1 = b2 + (size_t)e1 * DIM;
    const float* p2 = b2 + (size_t)e2 * DIM;
    float* o = out + (size_t)tok * DIM;
    for (int i = threadIdx.x; i < DIM; i += blockDim.x)
        o[i] = g1 * p1[i] + g2 * p2[i];
}

// ---------------- kernel: fp32 -> fp16 weight convert ----------------
__global__ void convert_half_kernel(const float* __restrict__ src,
                                    __half* __restrict__ dst, size_t n) {
    size_t idx = ((size_t)blockIdx.x * blockDim.x + threadIdx.x) * 8;
    if (idx < n) {
        float4 v0 = *(const float4*)(src + idx);
        float4 v1 = *(const float4*)(src + idx + 4);
        __half2 h[4];
        h[0] = __floats2half2_rn(v0.x, v0.y);
        h[1] = __floats2half2_rn(v0.z, v0.w);
        h[2] = __floats2half2_rn(v1.x, v1.y);
        h[3] = __floats2half2_rn(v1.z, v1.w);
        *(uint4*)(dst + idx) = *(uint4*)h;
    }
}

// ---------------- GEMM: fp16 mma.m16n8k16, 128x128x64 tiles, 3-stage cp.async ----------------
// 256 threads, 8 warps (4M x 2N), warp tile 32x64 (round-11 mainloop — best known).
// ebase: first expert handled by this launch (gridDim.y / RT experts, contiguous).
// PHASE 2 runs split-K via blockIdx.z (slices concurrent; atomic adds commute).
template<int KDIM, int NDIM, int PHASE, int SPLITK>
__global__ void __launch_bounds__(256, 2)
gemm_f16_kernel(const __half* __restrict__ Wh,
                const float* __restrict__ biasAll,
                float* __restrict__ out, int ebase) {
    constexpr int BM = 128, BN = 128, BK = 64, STAGES = 3;
    constexpr int KSLICE = KDIM / SPLITK;
    constexpr int ASTR = 144;
    constexpr int BSTR = 272;
    constexpr int ABYTES = BM * ASTR;
    constexpr int BBYTES = BK * BSTR;
    constexpr int STAGE  = ABYTES + BBYTES;

    extern __shared__ char smem_raw[];
    uint32_t sb = (uint32_t)__cvta_generic_to_shared(smem_raw);
    sb = (sb + 127u) & ~127u;

    const int e  = ebase + blockIdx.y / RT;
    const int rt = blockIdx.y % RT;
    const int cnt = g_cnt[e];
    if (rt * BM >= cnt) return;
    const int row0 = g_off[e] + rt * BM;
    int nrows = cnt - rt * BM; if (nrows > BM) nrows = BM;
    const int col0 = blockIdx.x * BN;
    const int k0   = blockIdx.z * KSLICE;

    const __half* Aptr = (PHASE == 1 ? g_Xh : g_Hh) + (size_t)row0 * KDIM + k0;
    const __half* Bptr = Wh + (size_t)e * KDIM * NDIM + (size_t)k0 * NDIM;

    const int tid = threadIdx.x;
    const int w = tid >> 5, lane = tid & 31;
    const int grp = lane >> 2, qid = lane & 3;
    const int wm = (w >> 1) * 32;
    const int wn = (w & 1) * 64;
    const int KT = KSLICE / BK;

    float acc[2][8][4];
    #pragma unroll
    for (int tm = 0; tm < 2; tm++)
        #pragma unroll
        for (int tn = 0; tn < 8; tn++)
            #pragma unroll
            for (int i = 0; i < 4; i++) acc[tm][tn][i] = 0.f;

    auto issue = [&](int kt) {
        if (kt < KT) {
            const int s = kt % STAGES;
            const uint32_t ab = sb + s * STAGE;
            const uint32_t bb = ab + ABYTES;
            const int kofs = kt * BK;
            #pragma unroll
            for (int j = 0; j < 4; j++) {
                const int v = tid + j * 256;
                const int r = v >> 3, c = v & 7;
                const bool ok = r < nrows;
                cp16(ab + r * ASTR + c * 16,
                     Aptr + (size_t)r * KDIM + kofs + c * 8, ok);
            }
            #pragma unroll
            for (int j = 0; j < 4; j++) {
                const int v = tid + j * 256;
                const int k = v >> 4, c = v & 15;
                cp16(bb + k * BSTR + c * 16,
                     Bptr + (size_t)(kofs + k) * NDIM + col0 + c * 8, true);
            }
        }
        CP_COMMIT();
    };

    issue(0); issue(1);

    const uint32_t a_lrow = lane & 15;
    const uint32_t a_lcol = (lane >> 4) * 16;
    const uint32_t b_lrow = lane & 15;
    const uint32_t b_lcol = (lane >> 4) * 16;

    for (int kt = 0; kt < KT; kt++) {
        CP_WAIT1();
        __syncthreads();
        issue(kt + 2);

        const int s = kt % STAGES;
        const uint32_t ab = sb + s * STAGE;
        const uint32_t bb = ab + ABYTES;

        #pragma unroll
        for (int ks = 0; ks < 4; ks++) {
            unsigned af[2][4], bf[4][4];
            #pragma unroll
            for (int mt = 0; mt < 2; mt++)
                ldsm_x4(af[mt], ab + (wm + mt * 16 + a_lrow) * ASTR + a_lcol + ks * 32);
            #pragma unroll
            for (int np = 0; np < 4; np++)
                ldsm_x4t(bf[np], bb + (ks * 16 + b_lrow) * BSTR + (wn + np * 16) * 2 + b_lcol);
            #pragma unroll
            for (int mt = 0; mt < 2; mt++)
                #pragma unroll
                for (int nt = 0; nt < 8; nt++)
                    mma_f16(acc[mt][nt], af[mt], &bf[nt >> 1][(nt & 1) * 2]);
        }
    }

    if (PHASE == 1) {
        const float* bias = biasAll + (size_t)e * NDIM + col0;
        #pragma unroll
        for (int mt = 0; mt < 2; mt++) {
            #pragma unroll
            for (int hf = 0; hf < 2; hf++) {
                const int rl = wm + mt * 16 + grp + hf * 8;
                if (rl < nrows) {
                    __half* hrow = g_Hh + (size_t)(row0 + rl) * NDIM + col0;
                    #pragma unroll
                    for (int nt = 0; nt < 8; nt++) {
                        const int c = wn + nt * 8 + qid * 2;
                        float v0 = gelu_exact(acc[mt][nt][hf*2    ] + bias[c]);
                        float v1 = gelu_exact(acc[mt][nt][hf*2 + 1] + bias[c + 1]);
                        *(__half2*)(hrow + c) = __floats2half2_rn(v0, v1);
                    }
                }
            }
        }
    } else {
        #pragma unroll
        for (int mt = 0; mt < 2; mt++) {
            #pragma unroll
            for (int hf = 0; hf < 2; hf++) {
                const int rl = wm + mt * 16 + grp + hf * 8;
                if (rl < nrows) {
                    const int p = row0 + rl;
                    const float g = g_rowgate[p];
                    float* orow = out + (size_t)g_rowtok[p] * DIM + col0;
                    #pragma unroll
                    for (int nt = 0; nt < 8; nt++) {
                        const int c = wn + nt * 8 + qid * 2;
                        red_add_v2(orow + c,
                                   g * acc[mt][nt][hf*2],
                                   g * acc[mt][nt][hf*2 + 1]);
                    }
                }
            }
        }
    }
}

// ---------------- launch: round-12 topology, gemm2 split-K = 2 ----------------
extern "C" void kernel_launch(void* const* d_in, const int* in_sizes, int n_in,
                              void* d_out, int out_size) {
    const float* x    = (const float*)d_in[0];
    const float* cent = (const float*)d_in[1];
    const float* W1   = (const float*)d_in[2];
    const float* b1   = (const float*)d_in[3];
    const float* W2   = (const float*)d_in[4];
    const float* b2   = (const float*)d_in[5];
    float* out = (float*)d_out;

    const int n = in_sizes[0] / DIM;   // 4096 tokens

    const int smem_bytes = 3 * 35840 + 128;   // ~105.1 KB -> 2 CTAs/SM
    static cudaStream_t sB = nullptr;
    static cudaEvent_t eFork = nullptr, eRoute = nullptr, eW1 = nullptr,
                       eW2 = nullptr, eOut = nullptr, e1A = nullptr, eJoin = nullptr;
    if (sB == nullptr) {
        cudaFuncSetAttribute(gemm_f16_kernel<DIM, DFF, 1, 1>,
                             cudaFuncAttributeMaxDynamicSharedMemorySize, smem_bytes);
        cudaFuncSetAttribute(gemm_f16_kernel<DFF, DIM, 2, 2>,
                             cudaFuncAttributeMaxDynamicSharedMemorySize, smem_bytes);
        cudaStreamCreateWithFlags(&sB, cudaStreamNonBlocking);
        cudaEventCreateWithFlags(&eFork,  cudaEventDisableTiming);
        cudaEventCreateWithFlags(&eRoute, cudaEventDisableTiming);
        cudaEventCreateWithFlags(&eW1,    cudaEventDisableTiming);
        cudaEventCreateWithFlags(&eW2,    cudaEventDisableTiming);
        cudaEventCreateWithFlags(&eOut,   cudaEventDisableTiming);
        cudaEventCreateWithFlags(&e1A,    cudaEventDisableTiming);
        cudaEventCreateWithFlags(&eJoin,  cudaEventDisableTiming);
    }

    __half* w1h; cudaGetSymbolAddress((void**)&w1h, g_W1h);
    __half* w2h; cudaGetSymbolAddress((void**)&w2h, g_W2h);

    const size_t welems = (size_t)NE * DIM * DFF;
    const int cblocks = (int)(welems / 8 / 256);

    // fork stream B
    cudaEventRecord(eFork, 0);
    cudaStreamWaitEvent(sB, eFork, 0);

    // ---- stream B: weight converts ----
    convert_half_kernel<<<cblocks, 256, 0, sB>>>(W1, w1h, welems);
    cudaEventRecord(eW1, sB);
    convert_half_kernel<<<cblocks, 256, 0, sB>>>(W2, w2h, welems);
    cudaEventRecord(eW2, sB);

    // ---- main stream: routing chain ----
    reset_kernel<<<1, 32>>>();
    route_kernel<<<n, 256>>>(x, cent);
    cudaEventRecord(eRoute, 0);
    scan_kernel<<<1, 1>>>();
    permute_kernel<<<2 * n, 256>>>(x);

    // ---- stream B: outinit (needs route only) ----
    cudaStreamWaitEvent(sB, eRoute, 0);
    outinit_kernel<<<n, 256, 0, sB>>>(b2, out);
    cudaEventRecord(eOut, sB);

    // ---- main stream: gemm1 experts 0-3, then 4-7 ----
    cudaStreamWaitEvent(0, eW1, 0);
    dim3 g1(DFF / 128, 4 * RT, 1);
    gemm_f16_kernel<DIM, DFF, 1, 1><<<g1, 256, smem_bytes>>>(w1h, b1, nullptr, 0);
    cudaEventRecord(e1A, 0);
    gemm_f16_kernel<DIM, DFF, 1, 1><<<g1, 256, smem_bytes>>>(w1h, b1, nullptr, 4);

    // ---- stream B: gemm2 experts 0-3 (overlaps gemm1 experts 4-7) ----
    cudaStreamWaitEvent(sB, e1A, 0);
    dim3 g2(DIM / 128, 4 * RT, 2);          // split-K x2 (was x4): halves atomic traffic
    gemm_f16_kernel<DFF, DIM, 2, 2><<<g2, 256, smem_bytes, sB>>>(w2h, nullptr, out, 0);
    cudaEventRecord(eJoin, sB);

    // ---- main stream: gemm2 experts 4-7 (after gemm1B; needs w2h + outinit) ----
    cudaStreamWaitEvent(0, eW2, 0);
    cudaStreamWaitEvent(0, eOut, 0);
    gemm_f16_kernel<DFF, DIM, 2, 2><<<g2, 256, smem_bytes>>>(w2h, nullptr, out, 4);

    // join stream B back to main
    cudaStreamWaitEvent(0, eJoin, 0);
}

// round 16
// speedup vs baseline: 1.0613x; 1.0198x over previous
#include <cuda_runtime.h>
#include <cuda_fp16.h>
#include <math.h>
#include <stdint.h>

#define NE 8
#define DIM 1024
#define DFF 4096
#define MAXN 4096
#define MAXA (2*MAXN)
#define RT 16   // row tiles per expert (max 2048 rows)

// ---------------- scratch (device globals: allocation-free) ----------------
__device__ __half g_Xtok[(size_t)MAXN * DIM];      // 8 MB  token-ordered fp16 x
__device__ __half g_Hh[(size_t)MAXA * DFF];        // 64 MB hidden post-GELU (fp16, permuted rows)
__device__ __half g_W1h[(size_t)NE * DIM * DFF];
__device__ __half g_W2h[(size_t)NE * DFF * DIM];
__device__ int   g_cnt[NE];
__device__ int   g_off[NE];
__device__ int   g_cur[NE];
__device__ int   g_tope[MAXA];
__device__ float g_topg[MAXA];
__device__ int   g_rowtok[MAXA];                   // permuted row -> token (gemm1 gather, gemm2 scatter)
__device__ float g_rowgate[MAXA];

// ---------------- helpers ----------------
__device__ __forceinline__ float gelu_exact(float v) {
    return 0.5f * v * (1.0f + erff(v * 0.70710678118654752f));
}
__device__ __forceinline__ void cp16(uint32_t saddr, const void* gsrc, bool pred) {
    int sz = pred ? 16 : 0;
    asm volatile("cp.async.cg.shared.global [%0], [%1], 16, %2;\n"
                 :: "r"(saddr), "l"(gsrc), "r"(sz));
}
#define CP_COMMIT() asm volatile("cp.async.commit_group;\n")
#define CP_WAIT1()  asm volatile("cp.async.wait_group 1;\n")

__device__ __forceinline__ void ldsm_x4(unsigned r[4], uint32_t addr) {
    asm volatile("ldmatrix.sync.aligned.m8n8.x4.shared.b16 {%0,%1,%2,%3}, [%4];"
                 : "=r"(r[0]), "=r"(r[1]), "=r"(r[2]), "=r"(r[3]) : "r"(addr));
}
__device__ __forceinline__ void ldsm_x4t(unsigned r[4], uint32_t addr) {
    asm volatile("ldmatrix.sync.aligned.m8n8.x4.trans.shared.b16 {%0,%1,%2,%3}, [%4];"
                 : "=r"(r[0]), "=r"(r[1]), "=r"(r[2]), "=r"(r[3]) : "r"(addr));
}
__device__ __forceinline__ void mma_f16(float c[4], const unsigned a[4], const unsigned b[2]) {
    asm volatile(
        "mma.sync.aligned.m16n8k16.row.col.f32.f16.f16.f32 "
        "{%0,%1,%2,%3}, {%4,%5,%6,%7}, {%8,%9}, {%0,%1,%2,%3};\n"
        : "+f"(c[0]), "+f"(c[1]), "+f"(c[2]), "+f"(c[3])
        : "r"(a[0]), "r"(a[1]), "r"(a[2]), "r"(a[3]), "r"(b[0]), "r"(b[1]));
}
__device__ __forceinline__ void red_add_v2(float* p, float a, float b) {
    asm volatile("red.global.add.v2.f32 [%0], {%1, %2};"
                 :: "l"(p), "f"(a), "f"(b) : "memory");
}

// ---------------- kernel 1: reset ----------------
__global__ void reset_kernel() {
    if (threadIdx.x < NE) g_cnt[threadIdx.x] = 0;
}

// ---------------- kernel 2: routing ----------------
// top-2 on SIGMOID GATES (saturate to 1.0f; logit std ~32), lowest-index
// tie-break to match jax.lax.top_k. (fp32 throughout — do not change.)
__global__ void route_kernel(const float* __restrict__ x,
                             const float* __restrict__ cent) {
    __shared__ float su[DIM];
    __shared__ float slog[NE];
    const int tok = blockIdx.x;
    const float* u = x + (size_t)tok * DIM;
    for (int i = threadIdx.x; i < DIM; i += blockDim.x) su[i] = u[i];
    __syncthreads();

    const int w = threadIdx.x >> 5, lane = threadIdx.x & 31;
    const float* c = cent + (size_t)w * DIM;
    float s = 0.f;
    for (int i = lane; i < DIM; i += 32) s += su[i] * c[i];
    #pragma unroll
    for (int o = 16; o; o >>= 1) s += __shfl_xor_sync(0xffffffffu, s, o);
    if (lane == 0) slog[w] = s;
    __syncthreads();

    if (threadIdx.x == 0) {
        float gate[NE];
        #pragma unroll
        for (int e = 0; e < NE; e++) gate[e] = 1.0f / (1.0f + expf(-slog[e]));
        int e1 = 0; float v1 = gate[0];
        #pragma unroll
        for (int e = 1; e < NE; e++) if (gate[e] > v1) { v1 = gate[e]; e1 = e; }
        int e2 = -1; float v2 = -1.0f;
        #pragma unroll
        for (int e = 0; e < NE; e++) if (e != e1 && gate[e] > v2) { v2 = gate[e]; e2 = e; }
        float inv = 1.0f / (v1 + v2);
        g_tope[2*tok + 0] = e1;  g_topg[2*tok + 0] = v1 * inv;
        g_tope[2*tok + 1] = e2;  g_topg[2*tok + 1] = v2 * inv;
        atomicAdd(&g_cnt[e1], 1);
        atomicAdd(&g_cnt[e2], 1);
    }
}

// ---------------- kernel 3: scan ----------------
__global__ void scan_kernel() {
    if (threadIdx.x == 0) {
        int o = 0;
        #pragma unroll
        for (int e = 0; e < NE; e++) { g_off[e] = o; g_cur[e] = o; o += g_cnt[e]; }
    }
}

// ---------------- kernel 4: permute INDEX ONLY (no data copy) ----------------
__global__ void permute_idx_kernel(int nassign) {
    const int a = blockIdx.x * blockDim.x + threadIdx.x;
    if (a < nassign) {
        int e = g_tope[a];
        int p = atomicAdd(&g_cur[e], 1);
        g_rowtok[p]  = a >> 1;
        g_rowgate[p] = g_topg[a];
    }
}

// ---------------- kernel 5: init output with gate-weighted b2 ----------------
__global__ void outinit_kernel(const float* __restrict__ b2,
                               float* __restrict__ out) {
    const int tok = blockIdx.x;
    const int e1 = g_tope[2*tok], e2 = g_tope[2*tok + 1];
    const float g1 = g_topg[2*tok], g2 = g_topg[2*tok + 1];
    const float* p1 = b2 + (size_t)e1 * DIM;
    const float* p2 = b2 + (size_t)e2 * DIM;
    float* o = out + (size_t)tok * DIM;
    for (int i = threadIdx.x; i < DIM; i += blockDim.x)
        o[i] = g1 * p1[i] + g2 * p2[i];
}

// ---------------- kernel: fp32 -> fp16 convert (weights AND token x) ----------------
__global__ void convert_half_kernel(const float* __restrict__ src,
                                    __half* __restrict__ dst, size_t n) {
    size_t idx = ((size_t)blockIdx.x * blockDim.x + threadIdx.x) * 8;
    if (idx < n) {
        float4 v0 = *(const float4*)(src + idx);
        float4 v1 = *(const float4*)(src + idx + 4);
        __half2 h[4];
        h[0] = __floats2half2_rn(v0.x, v0.y);
        h[1] = __floats2half2_rn(v0.z, v0.w);
        h[2] = __floats2half2_rn(v1.x, v1.y);
        h[3] = __floats2half2_rn(v1.z, v1.w);
        *(uint4*)(dst + idx) = *(uint4*)h;
    }
}

// ---------------- GEMM: fp16 mma.m16n8k16, 128x128x64 tiles, 3-stage cp.async ----------------
// 256 threads, 8 warps (4M x 2N), warp tile 32x64 (round-11 mainloop — best known).
// PHASE 1: A rows GATHERED from token-ordered g_Xtok via g_rowtok (indices
// preloaded once per thread; each row is a contiguous 2KB stream).
// PHASE 2 (split-K via blockIdx.z, slices concurrent): reads permuted g_Hh rows.
template<int KDIM, int NDIM, int PHASE, int SPLITK>
__global__ void __launch_bounds__(256, 2)
gemm_f16_kernel(const __half* __restrict__ Wh,
                const float* __restrict__ biasAll,
                float* __restrict__ out, int ebase) {
    constexpr int BM = 128, BN = 128, BK = 64, STAGES = 3;
    constexpr int KSLICE = KDIM / SPLITK;
    constexpr int ASTR = 144;
    constexpr int BSTR = 272;
    constexpr int ABYTES = BM * ASTR;
    constexpr int BBYTES = BK * BSTR;
    constexpr int STAGE  = ABYTES + BBYTES;

    extern __shared__ char smem_raw[];
    uint32_t sb = (uint32_t)__cvta_generic_to_shared(smem_raw);
    sb = (sb + 127u) & ~127u;

    const int e  = ebase + blockIdx.y / RT;
    const int rt = blockIdx.y % RT;
    const int cnt = g_cnt[e];
    if (rt * BM >= cnt) return;
    const int row0 = g_off[e] + rt * BM;
    int nrows = cnt - rt * BM; if (nrows > BM) nrows = BM;
    const int col0 = blockIdx.x * BN;
    const int k0   = blockIdx.z * KSLICE;

    const __half* Aptr = (PHASE == 1) ? (g_Xtok + k0)
                                      : (g_Hh + (size_t)row0 * KDIM + k0);
    const __half* Bptr = Wh + (size_t)e * KDIM * NDIM + (size_t)k0 * NDIM;

    const int tid = threadIdx.x;
    const int w = tid >> 5, lane = tid & 31;
    const int grp = lane >> 2, qid = lane & 3;
    const int wm = (w >> 1) * 32;
    const int wn = (w & 1) * 64;
    const int KT = KSLICE / BK;

    // PHASE 1: preload gather indices (constant across all K-iterations)
    int atok[4] = {0, 0, 0, 0};
    if (PHASE == 1) {
        #pragma unroll
        for (int j = 0; j < 4; j++) {
            int r = (tid >> 3) + j * 32;
            atok[j] = (r < nrows) ? g_rowtok[row0 + r] : 0;
        }
    }

    float acc[2][8][4];
    #pragma unroll
    for (int tm = 0; tm < 2; tm++)
        #pragma unroll
        for (int tn = 0; tn < 8; tn++)
            #pragma unroll
            for (int i = 0; i < 4; i++) acc[tm][tn][i] = 0.f;

    auto issue = [&](int kt) {
        if (kt < KT) {
            const int s = kt % STAGES;
            const uint32_t ab = sb + s * STAGE;
            const uint32_t bb = ab + ABYTES;
            const int kofs = kt * BK;
            #pragma unroll
            for (int j = 0; j < 4; j++) {
                const int v = tid + j * 256;
                const int r = v >> 3, c = v & 7;
                const bool ok = r < nrows;
                const __half* src = (PHASE == 1)
                    ? Aptr + (size_t)atok[j] * KDIM + kofs + c * 8
                    : Aptr + (size_t)r * KDIM + kofs + c * 8;
                cp16(ab + r * ASTR + c * 16, src, ok);
            }
            #pragma unroll
            for (int j = 0; j < 4; j++) {
                const int v = tid + j * 256;
                const int k = v >> 4, c = v & 15;
                cp16(bb + k * BSTR + c * 16,
                     Bptr + (size_t)(kofs + k) * NDIM + col0 + c * 8, true);
            }
        }
        CP_COMMIT();
    };

    issue(0); issue(1);

    const uint32_t a_lrow = lane & 15;
    const uint32_t a_lcol = (lane >> 4) * 16;
    const uint32_t b_lrow = lane & 15;
    const uint32_t b_lcol = (lane >> 4) * 16;

    for (int kt = 0; kt < KT; kt++) {
        CP_WAIT1();
        __syncthreads();
        issue(kt + 2);

        const int s = kt % STAGES;
        const uint32_t ab = sb + s * STAGE;
        const uint32_t bb = ab + ABYTES;

        #pragma unroll
        for (int ks = 0; ks < 4; ks++) {
            unsigned af[2][4], bf[4][4];
            #pragma unroll
            for (int mt = 0; mt < 2; mt++)
                ldsm_x4(af[mt], ab + (wm + mt * 16 + a_lrow) * ASTR + a_lcol + ks * 32);
            #pragma unroll
            for (int np = 0; np < 4; np++)
                ldsm_x4t(bf[np], bb + (ks * 16 + b_lrow) * BSTR + (wn + np * 16) * 2 + b_lcol);
            #pragma unroll
            for (int mt = 0; mt < 2; mt++)
                #pragma unroll
                for (int nt = 0; nt < 8; nt++)
                    mma_f16(acc[mt][nt], af[mt], &bf[nt >> 1][(nt & 1) * 2]);
        }
    }

    if (PHASE == 1) {
        const float* bias = biasAll + (size_t)e * NDIM + col0;
        #pragma unroll
        for (int mt = 0; mt < 2; mt++) {
            #pragma unroll
            for (int hf = 0; hf < 2; hf++) {
                const int rl = wm + mt * 16 + grp + hf * 8;
                if (rl < nrows) {
                    __half* hrow = g_Hh + (size_t)(row0 + rl) * NDIM + col0;
                    #pragma unroll
                    for (int nt = 0; nt < 8; nt++) {
                        const int c = wn + nt * 8 + qid * 2;
                        float v0 = gelu_exact(acc[mt][nt][hf*2    ] + bias[c]);
                        float v1 = gelu_exact(acc[mt][nt][hf*2 + 1] + bias[c + 1]);
                        *(__half2*)(hrow + c) = __floats2half2_rn(v0, v1);
                    }
                }
            }
        }
    } else {
        #pragma unroll
        for (int mt = 0; mt < 2; mt++) {
            #pragma unroll
            for (int hf = 0; hf < 2; hf++) {
                const int rl = wm + mt * 16 + grp + hf * 8;
                if (rl < nrows) {
                    const int p = row0 + rl;
                    const float g = g_rowgate[p];
                    float* orow = out + (size_t)g_rowtok[p] * DIM + col0;
                    #pragma unroll
                    for (int nt = 0; nt < 8; nt++) {
                        const int c = wn + nt * 8 + qid * 2;
                        red_add_v2(orow + c,
                                   g * acc[mt][nt][hf*2],
                                   g * acc[mt][nt][hf*2 + 1]);
                    }
                }
            }
        }
    }
}

// ---------------- launch: 3-stream fork (x-convert / weight-converts / routing) ----------------
extern "C" void kernel_launch(void* const* d_in, const int* in_sizes, int n_in,
                              void* d_out, int out_size) {
    const float* x    = (const float*)d_in[0];
    const float* cent = (const float*)d_in[1];
    const float* W1   = (const float*)d_in[2];
    const float* b1   = (const float*)d_in[3];
    const float* W2   = (const float*)d_in[4];
    const float* b2   = (const float*)d_in[5];
    float* out = (float*)d_out;

    const int n = in_sizes[0] / DIM;   // 4096 tokens

    const int smem_bytes = 3 * 35840 + 128;   // ~105.1 KB -> 2 CTAs/SM
    static cudaStream_t sB = nullptr, sC = nullptr;
    static cudaEvent_t eFork = nullptr, eRoute = nullptr, eW1 = nullptr,
                       eW2 = nullptr, eOut = nullptr, e1A = nullptr,
                       eJoin = nullptr, eX = nullptr;
    if (sB == nullptr) {
        cudaFuncSetAttribute(gemm_f16_kernel<DIM, DFF, 1, 1>,
                             cudaFuncAttributeMaxDynamicSharedMemorySize, smem_bytes);
        cudaFuncSetAttribute(gemm_f16_kernel<DFF, DIM, 2, 2>,
                             cudaFuncAttributeMaxDynamicSharedMemorySize, smem_bytes);
        cudaStreamCreateWithFlags(&sB, cudaStreamNonBlocking);
        cudaStreamCreateWithFlags(&sC, cudaStreamNonBlocking);
        cudaEventCreateWithFlags(&eFork,  cudaEventDisableTiming);
        cudaEventCreateWithFlags(&eRoute, cudaEventDisableTiming);
        cudaEventCreateWithFlags(&eW1,    cudaEventDisableTiming);
        cudaEventCreateWithFlags(&eW2,    cudaEventDisableTiming);
        cudaEventCreateWithFlags(&eOut,   cudaEventDisableTiming);
        cudaEventCreateWithFlags(&e1A,    cudaEventDisableTiming);
        cudaEventCreateWithFlags(&eJoin,  cudaEventDisableTiming);
        cudaEventCreateWithFlags(&eX,     cudaEventDisableTiming);
    }

    __half* w1h; cudaGetSymbolAddress((void**)&w1h, g_W1h);
    __half* w2h; cudaGetSymbolAddress((void**)&w2h, g_W2h);
    __half* xtok; cudaGetSymbolAddress((void**)&xtok, g_Xtok);

    const size_t welems = (size_t)NE * DIM * DFF;
    const size_t xelems = (size_t)n * DIM;
    const int cblocks = (int)(welems / 8 / 256);
    const int xblocks = (int)((xelems / 8 + 255) / 256);

    // fork streams B and C
    cudaEventRecord(eFork, 0);
    cudaStreamWaitEvent(sB, eFork, 0);
    cudaStreamWaitEvent(sC, eFork, 0);

    // ---- stream C: x -> fp16 token-ordered (routing-independent) ----
    convert_half_kernel<<<xblocks, 256, 0, sC>>>(x, xtok, xelems);
    cudaEventRecord(eX, sC);

    // ---- stream B: weight converts ----
    convert_half_kernel<<<cblocks, 256, 0, sB>>>(W1, w1h, welems);
    cudaEventRecord(eW1, sB);
    convert_half_kernel<<<cblocks, 256, 0, sB>>>(W2, w2h, welems);
    cudaEventRecord(eW2, sB);

    // ---- main stream: routing chain (index-only permute) ----
    reset_kernel<<<1, 32>>>();
    route_kernel<<<n, 256>>>(x, cent);
    cudaEventRecord(eRoute, 0);
    scan_kernel<<<1, 1>>>();
    permute_idx_kernel<<<(2 * n + 255) / 256, 256>>>(2 * n);

    // ---- stream B: outinit (needs route only) ----
    cudaStreamWaitEvent(sB, eRoute, 0);
    outinit_kernel<<<n, 256, 0, sB>>>(b2, out);
    cudaEventRecord(eOut, sB);

    // ---- main stream: gemm1 experts 0-3, then 4-7 (needs w1h + xtok + indices) ----
    cudaStreamWaitEvent(0, eW1, 0);
    cudaStreamWaitEvent(0, eX, 0);
    dim3 g1(DFF / 128, 4 * RT, 1);
    gemm_f16_kernel<DIM, DFF, 1, 1><<<g1, 256, smem_bytes>>>(w1h, b1, nullptr, 0);
    cudaEventRecord(e1A, 0);
    gemm_f16_kernel<DIM, DFF, 1, 1><<<g1, 256, smem_bytes>>>(w1h, b1, nullptr, 4);

    // ---- stream B: gemm2 experts 0-3 (overlaps gemm1 experts 4-7) ----
    cudaStreamWaitEvent(sB, e1A, 0);
    dim3 g2(DIM / 128, 4 * RT, 2);          // split-K x2
    gemm_f16_kernel<DFF, DIM, 2, 2><<<g2, 256, smem_bytes, sB>>>(w2h, nullptr, out, 0);
    cudaEventRecord(eJoin, sB);

    // ---- main stream: gemm2 experts 4-7 ----
    cudaStreamWaitEvent(0, eW2, 0);
    cudaStreamWaitEvent(0, eOut, 0);
    gemm_f16_kernel<DFF, DIM, 2, 2><<<g2, 256, smem_bytes>>>(w2h, nullptr, out, 4);

    // join stream B back to main
    cudaStreamWaitEvent(0, eJoin, 0);
}